// round 1
// baseline (speedup 1.0000x reference)
#include <cuda_runtime.h>
#include <math.h>
#include <stdint.h>

#define N 6144
#define D 128
#define INV_TAU 10.0f

// ---------------- device scratch (no allocations allowed) ----------------
__device__ float g_Fn[N * D];
__device__ float g_Mn[N * D];
__device__ float g_Pn[N * D];
__device__ float g_repr[2][N * D];     // already divided by max(rowsum,1)
__device__ float g_rowsum[2][N];
__device__ float g_pos[2][N];
__device__ float g_sumall[2][N];
__device__ float g_weights[N * 2];
__device__ float g_loss_acc;

// ---------------- K0: zero accumulators ----------------
__global__ void k_zero() {
    int idx = blockIdx.x * blockDim.x + threadIdx.x;
    int total = 2 * N;
    if (idx < total) {
        g_sumall[idx / N][idx % N] = 0.0f;
    }
    if (idx == 0) g_loss_acc = 0.0f;
}

// ---------------- K1: L2 normalize the three embeddings ----------------
__global__ void k_normalize(const float* __restrict__ embF,
                            const float* __restrict__ embM,
                            const float* __restrict__ embP) {
    int i = blockIdx.x;
    int which = blockIdx.y;
    const float* src = (which == 0) ? embF : (which == 1) ? embM : embP;
    float* dst = (which == 0) ? g_Fn : (which == 1) ? g_Mn : g_Pn;
    int t = threadIdx.x;  // 128
    float v = src[(size_t)i * D + t];
    __shared__ float red[128];
    red[t] = v * v;
    __syncthreads();
#pragma unroll
    for (int s = 64; s > 0; s >>= 1) {
        if (t < s) red[t] += red[t + s];
        __syncthreads();
    }
    float norm = fmaxf(sqrtf(red[0]), 1e-12f);
    dst[(size_t)i * D + t] = v / norm;
}

// ---------------- K2: per-row adjacency scan -> repr, rowsum, pos ----------------
// One block per (row, which). Scans the 24KB adjacency row once, builds the
// nonzero list in smem (~31 entries expected), then:
//   repr[i,:]  = sum_e val_e * emb[j_e,:]  / max(rowsum,1)
//   pos[i]     = sum_e val_e * exp(dot(Fn_i, nrm_{j_e}) / tau)
#define MAXNZ 768
__global__ __launch_bounds__(128) void k_repr_pos(
    const float* __restrict__ FM_adj, const float* __restrict__ FP_adj,
    const float* __restrict__ embM, const float* __restrict__ embP) {
    int i = blockIdx.x;
    int w = blockIdx.y;  // 0 = FM, 1 = FP
    const float* adj = (w == 0) ? FM_adj : FP_adj;
    const float* emb = (w == 0) ? embM : embP;
    const float* nrm = (w == 0) ? g_Mn : g_Pn;
    int t = threadIdx.x;  // 128

    __shared__ int   s_idx[MAXNZ];
    __shared__ float s_val[MAXNZ];
    __shared__ int   s_cnt;
    __shared__ float s_rowsum;
    __shared__ float s_pos;
    __shared__ float s_F[D];

    if (t == 0) { s_cnt = 0; s_rowsum = 0.0f; s_pos = 0.0f; }
    s_F[t] = g_Fn[(size_t)i * D + t];
    __syncthreads();

    const float4* arow = (const float4*)(adj + (size_t)i * N);
    float myrs = 0.0f;
    for (int c = t; c < N / 4; c += 128) {
        float4 v = arow[c];
        if (v.x != 0.0f) { int p = atomicAdd(&s_cnt, 1); if (p < MAXNZ) { s_idx[p] = c * 4 + 0; s_val[p] = v.x; } myrs += v.x; }
        if (v.y != 0.0f) { int p = atomicAdd(&s_cnt, 1); if (p < MAXNZ) { s_idx[p] = c * 4 + 1; s_val[p] = v.y; } myrs += v.y; }
        if (v.z != 0.0f) { int p = atomicAdd(&s_cnt, 1); if (p < MAXNZ) { s_idx[p] = c * 4 + 2; s_val[p] = v.z; } myrs += v.z; }
        if (v.w != 0.0f) { int p = atomicAdd(&s_cnt, 1); if (p < MAXNZ) { s_idx[p] = c * 4 + 3; s_val[p] = v.w; } myrs += v.w; }
    }
    atomicAdd(&s_rowsum, myrs);
    __syncthreads();

    int cnt = min(s_cnt, MAXNZ);
    float rs = s_rowsum;
    float denom = fmaxf(rs, 1.0f);

    // repr: thread t owns dim t
    float acc = 0.0f;
    for (int e = 0; e < cnt; ++e)
        acc += s_val[e] * emb[(size_t)s_idx[e] * D + t];
    g_repr[w][(size_t)i * D + t] = acc / denom;
    if (t == 0) g_rowsum[w][i] = rs;

    // pos: warp-per-entry dot products
    int lane = t & 31, warp = t >> 5;
    float lp = 0.0f;
    for (int e = warp; e < cnt; e += 4) {
        int j = s_idx[e];
        const float* nr = nrm + (size_t)j * D;
        float p = s_F[lane] * nr[lane]
                + s_F[lane + 32] * nr[lane + 32]
                + s_F[lane + 64] * nr[lane + 64]
                + s_F[lane + 96] * nr[lane + 96];
#pragma unroll
        for (int o = 16; o; o >>= 1) p += __shfl_xor_sync(0xffffffffu, p, o);
        if (lane == 0) lp += s_val[e] * __expf(p * INV_TAU);
    }
    if (lane == 0) atomicAdd(&s_pos, lp);
    __syncthreads();
    if (t == 0) g_pos[w][i] = s_pos;
}

// ---------------- K3: dense sim row-sum GEMMs (no output matrix) ----------------
// sumall_M[i] = sum_j exp(Fn_i . Mn_j / tau); same for P. Tiled fp32 GEMM with
// exp + row-reduce epilogue. Tiles stored K-major in smem for conflict-free
// float4 fragment reads.
#define BM 64
#define BN 64
#define BK 32
#define JT_PER_BLOCK 16
#define JCHUNKS 6  // 6 * 16 * 64 = 6144

__global__ __launch_bounds__(256) void k_simsum() {
    __shared__ __align__(16) float Fs[BK][BM + 4];
    __shared__ __align__(16) float Ms[BK][BN + 4];
    __shared__ __align__(16) float Ps[BK][BN + 4];
    __shared__ float redM[BM];
    __shared__ float redP[BM];

    int i0 = blockIdx.x * BM;
    int tid = threadIdx.x;
    int tx = tid & 15, ty = tid >> 4;

    float sM[4] = {0, 0, 0, 0}, sP[4] = {0, 0, 0, 0};

#pragma unroll 1
    for (int jt = 0; jt < JT_PER_BLOCK; ++jt) {
        int j0 = (blockIdx.y * JT_PER_BLOCK + jt) * BN;
        float accM[4][4], accP[4][4];
#pragma unroll
        for (int m = 0; m < 4; ++m)
#pragma unroll
            for (int n = 0; n < 4; ++n) { accM[m][n] = 0.0f; accP[m][n] = 0.0f; }

#pragma unroll 1
        for (int kc = 0; kc < D; kc += BK) {
            __syncthreads();
#pragma unroll
            for (int part = 0; part < 2; ++part) {
                int fid = part * 256 + tid;  // 0..511 float4 slots
                int r = fid >> 3;            // row within tile (BK/4 = 8 float4/row)
                int kq = fid & 7;
                float4 a = *(const float4*)&g_Fn[(size_t)(i0 + r) * D + kc + kq * 4];
                Fs[kq * 4 + 0][r] = a.x; Fs[kq * 4 + 1][r] = a.y;
                Fs[kq * 4 + 2][r] = a.z; Fs[kq * 4 + 3][r] = a.w;
                float4 b = *(const float4*)&g_Mn[(size_t)(j0 + r) * D + kc + kq * 4];
                Ms[kq * 4 + 0][r] = b.x; Ms[kq * 4 + 1][r] = b.y;
                Ms[kq * 4 + 2][r] = b.z; Ms[kq * 4 + 3][r] = b.w;
                float4 c = *(const float4*)&g_Pn[(size_t)(j0 + r) * D + kc + kq * 4];
                Ps[kq * 4 + 0][r] = c.x; Ps[kq * 4 + 1][r] = c.y;
                Ps[kq * 4 + 2][r] = c.z; Ps[kq * 4 + 3][r] = c.w;
            }
            __syncthreads();
#pragma unroll 8
            for (int k = 0; k < BK; ++k) {
                float4 a4 = *(const float4*)&Fs[k][ty * 4];
                float4 bM4 = *(const float4*)&Ms[k][tx * 4];
                float4 bP4 = *(const float4*)&Ps[k][tx * 4];
                float av[4] = {a4.x, a4.y, a4.z, a4.w};
                float bm[4] = {bM4.x, bM4.y, bM4.z, bM4.w};
                float bp[4] = {bP4.x, bP4.y, bP4.z, bP4.w};
#pragma unroll
                for (int m = 0; m < 4; ++m)
#pragma unroll
                    for (int n = 0; n < 4; ++n) {
                        accM[m][n] = fmaf(av[m], bm[n], accM[m][n]);
                        accP[m][n] = fmaf(av[m], bp[n], accP[m][n]);
                    }
            }
        }
        // epilogue: exp + row partial sums
#pragma unroll
        for (int m = 0; m < 4; ++m) {
            float tMv = 0.0f, tPv = 0.0f;
#pragma unroll
            for (int n = 0; n < 4; ++n) {
                tMv += __expf(accM[m][n] * INV_TAU);
                tPv += __expf(accP[m][n] * INV_TAU);
            }
            sM[m] += tMv;
            sP[m] += tPv;
        }
    }

    // cross-thread row reduction
    if (tid < BM) { redM[tid] = 0.0f; redP[tid] = 0.0f; }
    __syncthreads();
#pragma unroll
    for (int m = 0; m < 4; ++m) {
        atomicAdd(&redM[ty * 4 + m], sM[m]);
        atomicAdd(&redP[ty * 4 + m], sP[m]);
    }
    __syncthreads();
    if (tid < BM) {
        atomicAdd(&g_sumall[0][i0 + tid], redM[tid]);
        atomicAdd(&g_sumall[1][i0 + tid], redP[tid]);
    }
}

// ---------------- K4: MLP + softmax -> weights ----------------
__global__ __launch_bounds__(128) void k_mlp(const float* __restrict__ W1,
                                             const float* __restrict__ b1,
                                             const float* __restrict__ W2,
                                             const float* __restrict__ b2,
                                             float* __restrict__ out_weights) {
    int i = blockIdx.x;
    int t = threadIdx.x;  // 128
    __shared__ float feat[2 * D];
    __shared__ float r0[128], r1[128];
    feat[t] = g_repr[0][(size_t)i * D + t];
    feat[D + t] = g_repr[1][(size_t)i * D + t];
    __syncthreads();
    float h = b1[t];
#pragma unroll 8
    for (int k = 0; k < 2 * D; ++k) h = fmaf(feat[k], W1[k * D + t], h);
    h = fmaxf(h, 0.0f);
    r0[t] = h * W2[t * 2 + 0];
    r1[t] = h * W2[t * 2 + 1];
    __syncthreads();
#pragma unroll
    for (int s = 64; s > 0; s >>= 1) {
        if (t < s) { r0[t] += r0[t + s]; r1[t] += r1[t + s]; }
        __syncthreads();
    }
    if (t == 0) {
        float o0 = r0[0] + b2[0];
        float o1 = r1[0] + b2[1];
        float mx = fmaxf(o0, o1);
        float e0 = expf(o0 - mx);
        float e1 = expf(o1 - mx);
        float inv = 1.0f / (e0 + e1);
        float w0 = e0 * inv, w1 = e1 * inv;
        g_weights[2 * i] = w0;
        g_weights[2 * i + 1] = w1;
        out_weights[2 * i] = w0;
        out_weights[2 * i + 1] = w1;
    }
}

// ---------------- K5: loss reduction ----------------
__global__ __launch_bounds__(256) void k_loss() {
    int idx = blockIdx.x * blockDim.x + threadIdx.x;
    int stride = gridDim.x * blockDim.x;
    float term = 0.0f;
    for (int i = idx; i < N; i += stride) {
        float w0 = g_weights[2 * i], w1 = g_weights[2 * i + 1];
        float pm = g_pos[0][i], pp = g_pos[1][i];
        float sm = g_sumall[0][i], sp = g_sumall[1][i];
        float wp = w0 * pm + w1 * pp;
        float wn = w0 * (sm - pm) + w1 * (sp - pp);
        float nei = fmaxf(g_rowsum[0][i] + g_rowsum[1][i], 1.0f);
        float ratio = wp / (wp + wn) / nei;
        ratio = fmaxf(ratio, 1e-10f);
        term += -logf(ratio);
    }
    __shared__ float red[256];
    red[threadIdx.x] = term;
    __syncthreads();
#pragma unroll
    for (int s = 128; s > 0; s >>= 1) {
        if (threadIdx.x < s) red[threadIdx.x] += red[threadIdx.x + s];
        __syncthreads();
    }
    if (threadIdx.x == 0) atomicAdd(&g_loss_acc, red[0]);
}

__global__ void k_finalize(float* __restrict__ out) {
    out[0] = g_loss_acc / (float)N;
}

// ---------------- launch ----------------
extern "C" void kernel_launch(void* const* d_in, const int* in_sizes, int n_in,
                              void* d_out, int out_size) {
    const float* embF = (const float*)d_in[0];
    const float* embM = (const float*)d_in[1];
    const float* embP = (const float*)d_in[2];
    const float* FM_adj = (const float*)d_in[3];
    const float* FP_adj = (const float*)d_in[4];
    const float* W1 = (const float*)d_in[5];
    const float* b1 = (const float*)d_in[6];
    const float* W2 = (const float*)d_in[7];
    const float* b2 = (const float*)d_in[8];
    float* out = (float*)d_out;

    k_zero<<<(2 * N + 255) / 256, 256>>>();
    k_normalize<<<dim3(N, 3), 128>>>(embF, embM, embP);
    k_repr_pos<<<dim3(N, 2), 128>>>(FM_adj, FP_adj, embM, embP);
    k_simsum<<<dim3(N / BM, JCHUNKS), 256>>>();
    k_mlp<<<N, 128>>>(W1, b1, W2, b2, out + 1);
    k_loss<<<24, 256>>>();
    k_finalize<<<1, 1>>>(out);
}